// round 3
// baseline (speedup 1.0000x reference)
#include <cuda_runtime.h>
#include <math.h>

#define NTOK 2048
#define NHEAD 8
#define DK 512
#define CIN 256
#define HWSZ 64   // 8x8 spatial
#define OUTCH 64  // projection out channels

// ---------------- device scratch (no cudaMalloc allowed) ----------------
__device__ float g_qh[(size_t)NHEAD * NTOK * DK];
__device__ float g_kh[(size_t)NHEAD * NTOK * DK];
__device__ float g_vh[(size_t)NHEAD * NTOK * DK];
__device__ float g_o [(size_t)NHEAD * NTOK * DK];
__device__ float g_attn_scratch[(size_t)NHEAD * NTOK * NTOK];

// =====================================================================
// Kernel 1: per-sample projection.  For sample n:
//   Y[o][hw] = sum_c W[o][c] * x[n][c][hw] + b[o]   (64x256 @ 256x64)
// stored as heads: dst[h][n][d], h = o>>3, d = (o&7)*64 + hw
// =====================================================================
__global__ __launch_bounds__(256) void proj_kernel(
    const float* __restrict__ x, const float* __restrict__ W,
    const float* __restrict__ b, float* __restrict__ dst)
{
    __shared__ float Xs[64][68];   // [c'][hw]
    __shared__ float Ws[64][68];   // [o][c']
    const int n = blockIdx.x;
    const int t = threadIdx.x;
    const int to  = (t >> 4) * 4;   // 4 output channels
    const int thw = (t & 15) * 4;   // 4 spatial cols

    const float* xn = x + (size_t)n * CIN * HWSZ;
    float acc[4][4] = {};

    for (int cc = 0; cc < CIN; cc += 64) {
        __syncthreads();
        #pragma unroll
        for (int i = 0; i < 16; i++) {
            int e = i * 256 + t;
            int r = e >> 6, c = e & 63;
            Xs[r][c] = xn[(size_t)cc * 64 + e];           // x[n][cc+r][c]
            Ws[r][c] = W[(size_t)r * CIN + cc + c];       // W[r][cc+c]
        }
        __syncthreads();
        #pragma unroll
        for (int c1 = 0; c1 < 64; c1++) {
            float a0 = Ws[to + 0][c1];
            float a1 = Ws[to + 1][c1];
            float a2 = Ws[to + 2][c1];
            float a3 = Ws[to + 3][c1];
            float4 bv = *(const float4*)&Xs[c1][thw];
            acc[0][0] += a0 * bv.x; acc[0][1] += a0 * bv.y; acc[0][2] += a0 * bv.z; acc[0][3] += a0 * bv.w;
            acc[1][0] += a1 * bv.x; acc[1][1] += a1 * bv.y; acc[1][2] += a1 * bv.z; acc[1][3] += a1 * bv.w;
            acc[2][0] += a2 * bv.x; acc[2][1] += a2 * bv.y; acc[2][2] += a2 * bv.z; acc[2][3] += a2 * bv.w;
            acc[3][0] += a3 * bv.x; acc[3][1] += a3 * bv.y; acc[3][2] += a3 * bv.z; acc[3][3] += a3 * bv.w;
        }
    }

    #pragma unroll
    for (int i = 0; i < 4; i++) {
        int o = to + i;
        float bias = b[o];
        int h = o >> 3;
        int dbase = (o & 7) * 64;
        float* dp = dst + ((size_t)h * NTOK + n) * DK + dbase + thw;
        float4 outv = make_float4(acc[i][0] + bias, acc[i][1] + bias,
                                  acc[i][2] + bias, acc[i][3] + bias);
        *(float4*)dp = outv;
    }
}

// =====================================================================
// Kernel 2/4: 128x128 tiled SGEMM, double-buffered smem, batched over z.
//   B_NT=true : C[m][n] = alpha * sum_k A[m][k] * B[n][k]   (B row-major NxK)
//   B_NT=false: C[m][n] = alpha * sum_k A[m][k] * B[k][n]   (B row-major KxN)
// =====================================================================
template<bool B_NT>
__global__ __launch_bounds__(256) void gemm128x128(
    const float* __restrict__ A, const float* __restrict__ B, float* __restrict__ C,
    int K, int lda, int ldb, int ldc,
    long long sA, long long sB, long long sC, float alpha)
{
    __shared__ float As[2][8][128];
    __shared__ float Bs[2][8][128];

    const float* Ab = A + (long long)blockIdx.z * sA;
    const float* Bb = B + (long long)blockIdx.z * sB;
    float*       Cb = C + (long long)blockIdx.z * sC;

    const int m0 = blockIdx.y * 128;
    const int n0 = blockIdx.x * 128;
    const int t  = threadIdx.x;
    const int tx = t & 15, ty = t >> 4;

    const int arow = t >> 1;             // 0..127
    const int acol = (t & 1) * 4;        // 0 or 4
    const int brow = t >> 5;             // 0..7   (NN)
    const int bcol = (t & 31) * 4;       // 0..124 (NN)

    const float* Aptr = &Ab[(long long)(m0 + arow) * lda + acol];
    const float* Bptr = B_NT ? &Bb[(long long)(n0 + arow) * ldb + acol]
                             : &Bb[(long long)brow * ldb + n0 + bcol];
    const long long bstep = B_NT ? 8 : (long long)8 * ldb;

    float acc[8][8] = {};

    const int niter = K >> 3;

    // ---- prologue: stage tile 0 ----
    {
        float4 av = *(const float4*)Aptr;
        float4 bv = *(const float4*)Bptr;
        As[0][acol + 0][arow] = av.x; As[0][acol + 1][arow] = av.y;
        As[0][acol + 2][arow] = av.z; As[0][acol + 3][arow] = av.w;
        if (B_NT) {
            Bs[0][acol + 0][arow] = bv.x; Bs[0][acol + 1][arow] = bv.y;
            Bs[0][acol + 2][arow] = bv.z; Bs[0][acol + 3][arow] = bv.w;
        } else {
            *(float4*)&Bs[0][brow][bcol] = bv;
        }
    }
    __syncthreads();

    for (int it = 0; it < niter; it++) {
        const int buf = it & 1;

        // prefetch next tile from global BEFORE compute (latency overlap)
        float4 nav, nbv;
        const bool have_next = (it + 1 < niter);
        if (have_next) {
            nav = *(const float4*)(Aptr + (long long)(it + 1) * 8);
            nbv = *(const float4*)(Bptr + (long long)(it + 1) * bstep);
        }

        #pragma unroll
        for (int kk = 0; kk < 8; kk++) {
            float4 a0 = *(const float4*)&As[buf][kk][ty * 4];
            float4 a1 = *(const float4*)&As[buf][kk][ty * 4 + 64];
            float4 b0 = *(const float4*)&Bs[buf][kk][tx * 4];
            float4 b1 = *(const float4*)&Bs[buf][kk][tx * 4 + 64];
            float a[8] = {a0.x, a0.y, a0.z, a0.w, a1.x, a1.y, a1.z, a1.w};
            float bb[8] = {b0.x, b0.y, b0.z, b0.w, b1.x, b1.y, b1.z, b1.w};
            #pragma unroll
            for (int i = 0; i < 8; i++)
                #pragma unroll
                for (int j = 0; j < 8; j++)
                    acc[i][j] += a[i] * bb[j];
        }

        if (have_next) {
            const int nb = buf ^ 1;
            As[nb][acol + 0][arow] = nav.x; As[nb][acol + 1][arow] = nav.y;
            As[nb][acol + 2][arow] = nav.z; As[nb][acol + 3][arow] = nav.w;
            if (B_NT) {
                Bs[nb][acol + 0][arow] = nbv.x; Bs[nb][acol + 1][arow] = nbv.y;
                Bs[nb][acol + 2][arow] = nbv.z; Bs[nb][acol + 3][arow] = nbv.w;
            } else {
                *(float4*)&Bs[nb][brow][bcol] = nbv;
            }
            __syncthreads();
        }
    }

    #pragma unroll
    for (int i = 0; i < 8; i++) {
        int row = m0 + ty * 4 + (i & 3) + ((i & 4) ? 64 : 0);
        float4 o0 = make_float4(alpha * acc[i][0], alpha * acc[i][1],
                                alpha * acc[i][2], alpha * acc[i][3]);
        float4 o1 = make_float4(alpha * acc[i][4], alpha * acc[i][5],
                                alpha * acc[i][6], alpha * acc[i][7]);
        *(float4*)&Cb[(long long)row * ldc + n0 + tx * 4]      = o0;
        *(float4*)&Cb[(long long)row * ldc + n0 + 64 + tx * 4] = o1;
    }
}

// =====================================================================
// Kernel 3: in-place row softmax over 2048 columns (one block per row)
// =====================================================================
__global__ __launch_bounds__(256) void softmax_rows(float* __restrict__ attn)
{
    float4* p4 = (float4*)(attn + (long long)blockIdx.x * NTOK);
    const int t = threadIdx.x;
    __shared__ float red[8];

    float4 v0 = p4[t];
    float4 v1 = p4[t + 256];

    float m = fmaxf(fmaxf(fmaxf(v0.x, v0.y), fmaxf(v0.z, v0.w)),
                    fmaxf(fmaxf(v1.x, v1.y), fmaxf(v1.z, v1.w)));
    #pragma unroll
    for (int o = 16; o; o >>= 1) m = fmaxf(m, __shfl_xor_sync(0xffffffffu, m, o));
    if ((t & 31) == 0) red[t >> 5] = m;
    __syncthreads();
    if (t < 32) {
        float r = (t < 8) ? red[t] : -3.4e38f;
        #pragma unroll
        for (int o = 4; o; o >>= 1) r = fmaxf(r, __shfl_xor_sync(0xffffffffu, r, o));
        if (t == 0) red[0] = r;
    }
    __syncthreads();
    m = red[0];
    __syncthreads();

    v0.x = __expf(v0.x - m); v0.y = __expf(v0.y - m);
    v0.z = __expf(v0.z - m); v0.w = __expf(v0.w - m);
    v1.x = __expf(v1.x - m); v1.y = __expf(v1.y - m);
    v1.z = __expf(v1.z - m); v1.w = __expf(v1.w - m);

    float s = v0.x + v0.y + v0.z + v0.w + v1.x + v1.y + v1.z + v1.w;
    #pragma unroll
    for (int o = 16; o; o >>= 1) s += __shfl_xor_sync(0xffffffffu, s, o);
    if ((t & 31) == 0) red[t >> 5] = s;
    __syncthreads();
    if (t < 32) {
        float r = (t < 8) ? red[t] : 0.0f;
        #pragma unroll
        for (int o = 4; o; o >>= 1) r += __shfl_xor_sync(0xffffffffu, r, o);
        if (t == 0) red[0] = r;
    }
    __syncthreads();
    float inv = 1.0f / red[0];

    v0.x *= inv; v0.y *= inv; v0.z *= inv; v0.w *= inv;
    v1.x *= inv; v1.y *= inv; v1.z *= inv; v1.w *= inv;
    p4[t] = v0;
    p4[t + 256] = v1;
}

// =====================================================================
// Kernel 5: fc (1x1 conv) + residual + InstanceNorm, one block per sample.
//   y[c][hw] = sum_oc Wfc[c][oc]*att[oc][hw] + bfc[c] + q[n][c][hw]
//   out = (y - mean_hw) * rsqrt(var_hw + eps)
// att[oc][hw] = g_o[h=oc>>3][n][d=(oc&7)*64+hw]
// =====================================================================
#define K3_SMEM ((256 * 65 + 64 * 68 + 256 * 68) * 4)
__global__ __launch_bounds__(256) void fc_norm_kernel(
    const float* __restrict__ oatt, const float* __restrict__ Wfc,
    const float* __restrict__ bfc, const float* __restrict__ q,
    float* __restrict__ out)
{
    extern __shared__ float sm[];
    float* Wfs = sm;                 // 256 x 65
    float* att = Wfs + 256 * 65;     // 64 x 68
    float* ys  = att + 64 * 68;      // 256 x 68

    const int n = blockIdx.x;
    const int t = threadIdx.x;

    #pragma unroll 4
    for (int i = 0; i < 64; i++) {
        int e = i * 256 + t;
        Wfs[(e >> 6) * 65 + (e & 63)] = Wfc[e];
        ys[(e >> 6) * 68 + (e & 63)] = q[(size_t)n * 16384 + e];
    }
    #pragma unroll
    for (int i = 0; i < 16; i++) {
        int e = i * 256 + t;
        int oc = e >> 6, hw = e & 63;
        att[oc * 68 + hw] =
            oatt[((size_t)(oc >> 3) * NTOK + n) * DK + (oc & 7) * 64 + hw];
    }
    __syncthreads();

    const int c = t;
    float4 acc[16];
    #pragma unroll
    for (int j = 0; j < 16; j++) acc[j] = make_float4(0.f, 0.f, 0.f, 0.f);

    for (int oc = 0; oc < 64; oc++) {
        float w = Wfs[c * 65 + oc];
        const float4* arow = (const float4*)&att[oc * 68];
        #pragma unroll
        for (int j = 0; j < 16; j++) {
            float4 v = arow[j];
            acc[j].x += w * v.x; acc[j].y += w * v.y;
            acc[j].z += w * v.z; acc[j].w += w * v.w;
        }
    }

    float bias = bfc[c];
    float4* yrow = (float4*)&ys[c * 68];
    float s = 0.f, s2 = 0.f;
    #pragma unroll
    for (int j = 0; j < 16; j++) {
        float4 r = yrow[j];
        float4 a = acc[j];
        a.x += bias + r.x; a.y += bias + r.y;
        a.z += bias + r.z; a.w += bias + r.w;
        acc[j] = a;
        s  += a.x + a.y + a.z + a.w;
        s2 += a.x * a.x + a.y * a.y + a.z * a.z + a.w * a.w;
    }
    float mean = s * (1.0f / 64.0f);
    float var  = s2 * (1.0f / 64.0f) - mean * mean;
    float inv  = rsqrtf(var + 1e-5f);
    #pragma unroll
    for (int j = 0; j < 16; j++) {
        float4 a = acc[j];
        a.x = (a.x - mean) * inv; a.y = (a.y - mean) * inv;
        a.z = (a.z - mean) * inv; a.w = (a.w - mean) * inv;
        yrow[j] = a;
    }
    __syncthreads();
    #pragma unroll 4
    for (int i = 0; i < 64; i++) {
        int e = i * 256 + t;
        out[(size_t)n * 16384 + e] = ys[(e >> 6) * 68 + (e & 63)];
    }
}

// =====================================================================
extern "C" void kernel_launch(void* const* d_in, const int* in_sizes, int n_in,
                              void* d_out, int out_size)
{
    const float* q   = (const float*)d_in[0];
    const float* k   = (const float*)d_in[1];
    const float* v   = (const float*)d_in[2];
    const float* Wq  = (const float*)d_in[3];
    const float* bq  = (const float*)d_in[4];
    const float* Wk  = (const float*)d_in[5];
    const float* bk  = (const float*)d_in[6];
    const float* Wv  = (const float*)d_in[7];
    const float* bv  = (const float*)d_in[8];
    const float* Wfc = (const float*)d_in[9];
    const float* bfc = (const float*)d_in[10];
    float* out = (float*)d_out;

    float *p_qh, *p_kh, *p_vh, *p_o, *p_attn_scr;
    cudaGetSymbolAddress((void**)&p_qh, g_qh);
    cudaGetSymbolAddress((void**)&p_kh, g_kh);
    cudaGetSymbolAddress((void**)&p_vh, g_vh);
    cudaGetSymbolAddress((void**)&p_o,  g_o);
    cudaGetSymbolAddress((void**)&p_attn_scr, g_attn_scratch);

    const size_t OUT_ELEMS  = (size_t)NTOK * CIN * HWSZ;          // 33554432
    const size_t ATTN_ELEMS = (size_t)NHEAD * NTOK * NTOK;        // 33554432
    // attn goes into d_out if it's part of the output, else into scratch
    float* attn = ((size_t)out_size >= OUT_ELEMS + ATTN_ELEMS)
                      ? out + OUT_ELEMS : p_attn_scr;

    // 1) projections
    proj_kernel<<<NTOK, 256>>>(q, Wq, bq, p_qh);
    proj_kernel<<<NTOK, 256>>>(k, Wk, bk, p_kh);
    proj_kernel<<<NTOK, 256>>>(v, Wv, bv, p_vh);

    // 2) scores = (Q K^T) / sqrt(512)
    {
        dim3 grid(NTOK / 128, NTOK / 128, NHEAD);
        gemm128x128<true><<<grid, 256>>>(
            p_qh, p_kh, attn, DK, DK, DK, NTOK,
            (long long)NTOK * DK, (long long)NTOK * DK, (long long)NTOK * NTOK,
            0.04419417382415922f /* 1/sqrt(512) */);
    }

    // 3) softmax over keys, in place
    softmax_rows<<<NHEAD * NTOK, 256>>>(attn);

    // 4) O = P @ V
    {
        dim3 grid(DK / 128, NTOK / 128, NHEAD);
        gemm128x128<false><<<grid, 256>>>(
            attn, p_vh, p_o, NTOK, NTOK, DK, DK,
            (long long)NTOK * NTOK, (long long)NTOK * DK, (long long)NTOK * DK,
            1.0f);
    }

    // 5) fc + residual + instance norm
    cudaFuncSetAttribute(fc_norm_kernel,
                         cudaFuncAttributeMaxDynamicSharedMemorySize, K3_SMEM);
    fc_norm_kernel<<<NTOK, 256, K3_SMEM>>>(p_o, Wfc, bfc, q, out);
}